// round 1
// baseline (speedup 1.0000x reference)
#include <cuda_runtime.h>
#include <stdint.h>

#define N_TOK 16384
#define K_CODE 8192
#define DIM 64
#define DECAYF 0.99f
#define OMDF 0.01f
#define EPSF 1e-5f

// scratch (device globals: no allocations allowed)
__device__ float g_halfc[K_CODE];          // 0.5*||c||^2
__device__ float g_pval[4 * N_TOK];        // partial min value per code-split
__device__ int   g_pidx[4 * N_TOK];        // partial argmin per code-split
__device__ int   g_idx[N_TOK];             // final argmin
__device__ float g_wacc[K_CODE * DIM];     // scatter-add accumulator
__device__ float g_cnt[K_CODE];            // histogram

// ---------------------------------------------------------------------------
// 0.5 * ||c||^2 per code
__global__ __launch_bounds__(256) void k_half(const float* __restrict__ cb) {
    int k = blockIdx.x * 256 + threadIdx.x;
    const float4* c4 = (const float4*)(cb + (size_t)k * DIM);
    float s = 0.f;
#pragma unroll
    for (int i = 0; i < 16; i++) {
        float4 v = c4[i];
        s += v.x * v.x + v.y * v.y + v.z * v.z + v.w * v.w;
    }
    g_halfc[k] = 0.5f * s;
}

// ---------------------------------------------------------------------------
// Distance/argmin kernel. grid = (4 code-splits, 128 token-blocks), 128 thr.
// Block tile: 128 tokens x 32 codes, thread tile 8 tokens x 4 codes.
// Both SMEM tiles k-major for conflict-free float4 loads.
// Also zero-fills the 'discrete' output region and the scratch accumulators,
// trickled through the idle LSU/DRAM pipes.
__global__ __launch_bounds__(128) void k_dist(const float* __restrict__ x,
                                              const float* __restrict__ cb,
                                              float* __restrict__ discrete) {
    __shared__ float As[64 * 128];   // As[k][token]
    __shared__ float Bs[64 * 32];    // Bs[k][code]

    const int tid = threadIdx.x;
    const int bx = blockIdx.x;               // code split 0..3
    const int by = blockIdx.y;               // token block 0..127
    const int blin = by * 4 + bx;            // 0..511
    const int tg = tid >> 3;                 // token group 0..15
    const int cg = tid & 7;                  // code group 0..7

    const float4 z4 = make_float4(0.f, 0.f, 0.f, 0.f);

    // zero scratch accumulators (grid-stride over 512*128 = 65536 threads)
    {
        const int g = blin * 128 + tid;
        float4* w4 = (float4*)g_wacc;        // 131072 float4
        w4[g] = z4;
        w4[g + 65536] = z4;
        if (g < 2048) ((float4*)g_cnt)[g] = z4;   // 8192 floats
    }

    // load x tile (128 tokens x 64 dims) transposed into As[k][t]
    const float4* x4 = (const float4*)x;
    const int m0 = by * 128;
#pragma unroll
    for (int it = 0; it < 16; it++) {
        int lin = tid + it * 128;
        int t = lin & 127, kq = lin >> 7;
        float4 v = x4[(size_t)(m0 + t) * 16 + kq];
        As[(kq * 4 + 0) * 128 + t] = v.x;
        As[(kq * 4 + 1) * 128 + t] = v.y;
        As[(kq * 4 + 2) * 128 + t] = v.z;
        As[(kq * 4 + 3) * 128 + t] = v.w;
    }
    __syncthreads();

    float minv[8];
    int   mini[8];
#pragma unroll
    for (int i = 0; i < 8; i++) { minv[i] = 3.402823466e38f; mini[i] = 0; }

    // discrete zero-fill slice for this block: 65536 float4 (262144 floats)
    float4* dz = (float4*)discrete + (size_t)blin * 65536;

    const float4* cb4 = (const float4*)cb;
    const float4* h4 = (const float4*)g_halfc;
    const float4* As4 = (const float4*)As;
    const float4* Bs4 = (const float4*)Bs;
    const int cbase = bx * 2048;

    for (int tile = 0; tile < 64; tile++) {
        const int c0 = cbase + tile * 32;
        // load codebook tile (32 codes x 64 dims) transposed into Bs[k][c]
#pragma unroll
        for (int it = 0; it < 4; it++) {
            int lin = tid + it * 128;
            int c = lin & 31, kq = lin >> 5;
            float4 v = cb4[(size_t)(c0 + c) * 16 + kq];
            Bs[(kq * 4 + 0) * 32 + c] = v.x;
            Bs[(kq * 4 + 1) * 32 + c] = v.y;
            Bs[(kq * 4 + 2) * 32 + c] = v.z;
            Bs[(kq * 4 + 3) * 32 + c] = v.w;
        }
        __syncthreads();

        float acc[8][4];
#pragma unroll
        for (int i = 0; i < 8; i++)
#pragma unroll
            for (int j = 0; j < 4; j++) acc[i][j] = 0.f;

#pragma unroll 16
        for (int k = 0; k < 64; k++) {
            float4 a0 = As4[k * 32 + tg * 2];
            float4 a1 = As4[k * 32 + tg * 2 + 1];
            float4 b  = Bs4[k * 8 + cg];
            float a[8] = {a0.x, a0.y, a0.z, a0.w, a1.x, a1.y, a1.z, a1.w};
            float bb[4] = {b.x, b.y, b.z, b.w};
#pragma unroll
            for (int i = 0; i < 8; i++)
#pragma unroll
                for (int j = 0; j < 4; j++)
                    acc[i][j] = fmaf(a[i], bb[j], acc[i][j]);
        }
        __syncthreads();

        // trickle zero-fill (8 STG.128 per thread per tile -> 512 total)
#pragma unroll
        for (int r = 0; r < 8; r++) dz[(tile * 8 + r) * 128 + tid] = z4;

        // score = 0.5||c||^2 - x.c ; running argmin (ascending idx, strict <)
        float4 h = h4[(c0 >> 2) + cg];
        float hh[4] = {h.x, h.y, h.z, h.w};
        const int cb0 = c0 + cg * 4;
#pragma unroll
        for (int i = 0; i < 8; i++)
#pragma unroll
            for (int j = 0; j < 4; j++) {
                float s = hh[j] - acc[i][j];
                if (s < minv[i]) { minv[i] = s; mini[i] = cb0 + j; }
            }
    }

    // reduce over the 8 code-group lanes (width-8 subgroups), lowest idx on tie
#pragma unroll
    for (int i = 0; i < 8; i++) {
        float v = minv[i];
        int id = mini[i];
#pragma unroll
        for (int off = 4; off; off >>= 1) {
            float ov = __shfl_xor_sync(0xffffffffu, v, off, 8);
            int oi = __shfl_xor_sync(0xffffffffu, id, off, 8);
            if (ov < v || (ov == v && oi < id)) { v = ov; id = oi; }
        }
        if (cg == 0) {
            int tok = m0 + tg * 8 + i;
            g_pval[bx * N_TOK + tok] = v;
            g_pidx[bx * N_TOK + tok] = id;
        }
    }
}

// ---------------------------------------------------------------------------
// merge the 4 code-split partial argmins (splits cover ascending idx ranges)
__global__ __launch_bounds__(256) void k_merge() {
    int n = blockIdx.x * 256 + threadIdx.x;
    float v = g_pval[n];
    int id = g_pidx[n];
#pragma unroll
    for (int s = 1; s < 4; s++) {
        float ov = g_pval[s * N_TOK + n];
        int oi = g_pidx[s * N_TOK + n];
        if (ov < v || (ov == v && oi < id)) { v = ov; id = oi; }
    }
    g_idx[n] = id;
}

// ---------------------------------------------------------------------------
// scatter: one-hot ones, quantized gather, histogram, weight scatter-add
__global__ __launch_bounds__(256) void k_scatter(const float* __restrict__ x,
                                                 const float* __restrict__ cb,
                                                 float* __restrict__ discrete,
                                                 float* __restrict__ quant) {
    int gid = blockIdx.x * 256 + threadIdx.x;  // 0 .. 1048575
    int n = gid >> 6, d = gid & 63;
    int k = g_idx[n];
    quant[gid] = cb[k * DIM + d];
    atomicAdd(&g_wacc[k * DIM + d], x[gid]);
    if (d == 0) {
        atomicAdd(&g_cnt[k], 1.0f);
        discrete[(size_t)n * K_CODE + k] = 1.0f;
    }
}

// ---------------------------------------------------------------------------
__global__ __launch_bounds__(256) void k_count(const float* __restrict__ ema_count,
                                               float* __restrict__ out_count) {
    int k = blockIdx.x * 256 + threadIdx.x;
    float v = ema_count[k] * DECAYF + g_cnt[k] * OMDF;
    out_count[k] = (v + EPSF) / (32.0f + 8192.0f * EPSF) * 32.0f;
}

__global__ __launch_bounds__(256) void k_final(const float* __restrict__ ema_weight,
                                               const float* __restrict__ out_count,
                                               float* __restrict__ out_weight,
                                               float* __restrict__ out_codebook) {
    int gid = blockIdx.x * 256 + threadIdx.x;  // 0 .. 524287
    int k = gid >> 6;
    float nw = ema_weight[gid] * DECAYF + g_wacc[gid] * OMDF;
    out_weight[gid] = nw;
    out_codebook[gid] = nw / out_count[k];
}

// ---------------------------------------------------------------------------
extern "C" void kernel_launch(void* const* d_in, const int* in_sizes, int n_in,
                              void* d_out, int out_size) {
    const float* x = (const float*)d_in[0];           // 16384 x 64
    const float* cb = (const float*)d_in[1];          // 8192 x 64
    const float* ema_count = (const float*)d_in[2];   // 8192
    const float* ema_weight = (const float*)d_in[3];  // 8192 x 64

    float* out = (float*)d_out;
    float* o_disc = out;                                   // 134217728
    float* o_quant = o_disc + (size_t)N_TOK * K_CODE;      // 1048576
    float* o_cnt = o_quant + (size_t)N_TOK * DIM;          // 8192
    float* o_w = o_cnt + K_CODE;                           // 524288
    float* o_cb = o_w + (size_t)K_CODE * DIM;              // 524288

    k_half<<<K_CODE / 256, 256>>>(cb);
    k_dist<<<dim3(4, 128, 1), 128>>>(x, cb, o_disc);
    k_merge<<<N_TOK / 256, 256>>>();
    k_scatter<<<(N_TOK * DIM) / 256, 256>>>(x, cb, o_disc, o_quant);
    k_count<<<K_CODE / 256, 256>>>(ema_count, o_cnt);
    k_final<<<(K_CODE * DIM) / 256, 256>>>(ema_weight, o_cnt, o_w, o_cb);
}